// round 12
// baseline (speedup 1.0000x reference)
#include <cuda_runtime.h>
#include <cuda_fp16.h>
#include <cstdint>

#define NN 8192
#define DD 128
#define MAXNB 512
#define NEG_SLOPE 0.2f

#define BUILD_BLOCKS 512     // 512-thread blocks, 16 rows each
#define GEMM_BLOCKS  128     // BM=64

// ---------------- device scratch (no allocations allowed) ----------------
__device__ __half g_h0[(size_t)NN * DD];   // layer-0 features, fp16
__device__ __half g_h1[(size_t)NN * DD];   // layer-1 features, fp16
__device__ float g_asrc0[NN];
__device__ float g_adst0[NN];
__device__ float g_asrc1[NN];
__device__ float g_adst1[NN];
__device__ int   g_col[(size_t)NN * MAXNB];
__device__ int   g_cnt[NN];

// ---------------- adjacency scan body --------------------------------------
__device__ __forceinline__ void build_row(const float* __restrict__ adj, int row_id, int lane) {
    const float4* row = reinterpret_cast<const float4*>(adj + (size_t)row_id * NN);
    int* col = g_col + (size_t)row_id * MAXNB;
    const unsigned ltmask = (1u << lane) - 1u;
    int cnt = 0;
    #pragma unroll 2
    for (int j0 = 0; j0 < NN; j0 += 128) {
        float4 v = row[(j0 >> 2) + lane];
        int base = j0 + lane * 4;
        unsigned m0 = __ballot_sync(0xffffffffu, v.x != 0.0f);
        unsigned m1 = __ballot_sync(0xffffffffu, v.y != 0.0f);
        unsigned m2 = __ballot_sync(0xffffffffu, v.z != 0.0f);
        unsigned m3 = __ballot_sync(0xffffffffu, v.w != 0.0f);
        if (v.x != 0.0f) { int p = cnt + __popc(m0 & ltmask); if (p < MAXNB) col[p] = base + 0; }
        cnt += __popc(m0);
        if (v.y != 0.0f) { int p = cnt + __popc(m1 & ltmask); if (p < MAXNB) col[p] = base + 1; }
        cnt += __popc(m1);
        if (v.z != 0.0f) { int p = cnt + __popc(m2 & ltmask); if (p < MAXNB) col[p] = base + 2; }
        cnt += __popc(m2);
        if (v.w != 0.0f) { int p = cnt + __popc(m3 & ltmask); if (p < MAXNB) col[p] = base + 3; }
        cnt += __popc(m3);
    }
    if (lane == 0) g_cnt[row_id] = cnt < MAXNB ? cnt : MAXNB;
}

// ---------------- GEMM body (BM=64, 512 thr, 4x4/thread) -------------------
__device__ __forceinline__ void gemm_tile(const float* __restrict__ X,
                                          const float* __restrict__ W,
                                          const float* __restrict__ att_src,
                                          const float* __restrict__ att_dst,
                                          __half* __restrict__ Hh,
                                          int rowBase) {
    __shared__ float As[16][64];
    __shared__ float Bs[16][128];
    const int tid  = threadIdx.x;
    const int lane = tid & 31;
    const int wrp  = tid >> 5;

    float acc[4][4];
    #pragma unroll
    for (int i = 0; i < 4; i++)
        #pragma unroll
        for (int j = 0; j < 4; j++) acc[i][j] = 0.0f;

    for (int k0 = 0; k0 < DD; k0 += 16) {
        {
            int r  = tid >> 3;
            int kq = (tid & 7) * 2;
            float2 v = *reinterpret_cast<const float2*>(
                &X[(size_t)(rowBase + r) * DD + k0 + kq]);
            As[kq + 0][r] = v.x;
            As[kq + 1][r] = v.y;
        }
        {
            int kr = tid >> 5;
            int cq = (tid & 31) * 4;
            *reinterpret_cast<float4*>(&Bs[kr][cq]) =
                *reinterpret_cast<const float4*>(&W[(size_t)(k0 + kr) * DD + cq]);
        }
        __syncthreads();
        #pragma unroll
        for (int k = 0; k < 16; k++) {
            float4 a4 = *reinterpret_cast<const float4*>(&As[k][wrp * 4]);
            float4 b4 = *reinterpret_cast<const float4*>(&Bs[k][lane * 4]);
            float a[4] = {a4.x, a4.y, a4.z, a4.w};
            float b[4] = {b4.x, b4.y, b4.z, b4.w};
            #pragma unroll
            for (int i = 0; i < 4; i++)
                #pragma unroll
                for (int j = 0; j < 4; j++)
                    acc[i][j] = fmaf(a[i], b[j], acc[i][j]);
        }
        __syncthreads();
    }

    #pragma unroll
    for (int i = 0; i < 4; i++) {
        __half2 p0 = __float22half2_rn(make_float2(acc[i][0], acc[i][1]));
        __half2 p1 = __float22half2_rn(make_float2(acc[i][2], acc[i][3]));
        uint2 pk;
        pk.x = *reinterpret_cast<unsigned*>(&p0);
        pk.y = *reinterpret_cast<unsigned*>(&p1);
        *reinterpret_cast<uint2*>(&Hh[(size_t)(rowBase + wrp * 4 + i) * DD + lane * 4]) = pk;
    }

    float4 s4 = *reinterpret_cast<const float4*>(&att_src[lane * 4]);
    float4 d4 = *reinterpret_cast<const float4*>(&att_dst[lane * 4]);
    #pragma unroll
    for (int i = 0; i < 4; i++) {
        float ps = acc[i][0] * s4.x + acc[i][1] * s4.y + acc[i][2] * s4.z + acc[i][3] * s4.w;
        float pd = acc[i][0] * d4.x + acc[i][1] * d4.y + acc[i][2] * d4.z + acc[i][3] * d4.w;
        #pragma unroll
        for (int o = 16; o > 0; o >>= 1) {
            ps += __shfl_xor_sync(0xffffffffu, ps, o);
            pd += __shfl_xor_sync(0xffffffffu, pd, o);
        }
        if (lane == 0) {
            g_asrc0[rowBase + wrp * 4 + i] = ps;
            g_adst0[rowBase + wrp * 4 + i] = pd;
        }
    }
}

// ---------------- fused: adjacency scan (grid head) + layer-0 GEMM ---------
__global__ __launch_bounds__(512) void fused_build_gemm(const float* __restrict__ adj,
                                                        const float* __restrict__ X,
                                                        const float* __restrict__ W,
                                                        const float* __restrict__ att_src,
                                                        const float* __restrict__ att_dst,
                                                        __half* __restrict__ Hh) {
    if (blockIdx.x < BUILD_BLOCKS) {
        int row_id = (blockIdx.x * 512 + threadIdx.x) >> 5;
        build_row(adj, row_id, threadIdx.x & 31);
    } else {
        gemm_tile(X, W, att_src, att_dst, Hh, (blockIdx.x - BUILD_BLOCKS) * 64);
    }
}

// ---------------- shared aggregate core ------------------------------------
// Computes s = (softmax-weighted neighbor sum)[channel tid] * inv for row i.
// Returns the pre-bias aggregate and the normalizer via out params.
__device__ __forceinline__ float agg_core(const __half* __restrict__ Hh,
                                          const float* __restrict__ asrc,
                                          const float* __restrict__ adst,
                                          int i, float* se, int* sc,
                                          float* reds, float (*accs)[DD]) {
    const int tid  = threadIdx.x;
    const int lane = tid & 31;
    const int w    = tid >> 5;
    const int half = lane >> 4;
    const int pos  = lane & 15;

    const int cnt = g_cnt[i];
    const float adst_i = adst[i];
    const int* __restrict__ col = g_col + (size_t)i * MAXNB;

    float lsum = 0.0f;
    for (int k = tid; k < cnt; k += 128) {
        int j = col[k];
        sc[k] = j;
        float e = asrc[j] + adst_i;
        e = e >= 0.0f ? e : NEG_SLOPE * e;
        float wv = __expf(e);
        se[k] = wv;
        lsum += wv;
    }
    if (tid < 16) { se[cnt + tid] = 0.0f; sc[cnt + tid] = 0; }
    #pragma unroll
    for (int o = 16; o > 0; o >>= 1)
        lsum += __shfl_xor_sync(0xffffffffu, lsum, o);
    if (lane == 0) reds[w] = lsum;
    __syncthreads();
    const float inv = 1.0f / (reds[0] + reds[1] + reds[2] + reds[3]);

    const uint4* __restrict__ H4 = reinterpret_cast<const uint4*>(Hh);
    float acc[8];
    #pragma unroll
    for (int c = 0; c < 8; c++) acc[c] = 0.0f;

    #define ACC8(wv, u) do {                                              \
        __half2 q0 = *reinterpret_cast<const __half2*>(&(u).x);           \
        __half2 q1 = *reinterpret_cast<const __half2*>(&(u).y);           \
        __half2 q2 = *reinterpret_cast<const __half2*>(&(u).z);           \
        __half2 q3 = *reinterpret_cast<const __half2*>(&(u).w);           \
        float2 f0 = __half22float2(q0); float2 f1 = __half22float2(q1);   \
        float2 f2 = __half22float2(q2); float2 f3 = __half22float2(q3);   \
        acc[0] = fmaf((wv), f0.x, acc[0]); acc[1] = fmaf((wv), f0.y, acc[1]); \
        acc[2] = fmaf((wv), f1.x, acc[2]); acc[3] = fmaf((wv), f1.y, acc[3]); \
        acc[4] = fmaf((wv), f2.x, acc[4]); acc[5] = fmaf((wv), f2.y, acc[5]); \
        acc[6] = fmaf((wv), f3.x, acc[6]); acc[7] = fmaf((wv), f3.y, acc[7]); \
    } while (0)

    for (int k = w * 2 + half; k < cnt; k += 16) {
        float w0 = se[k];
        float w1 = se[k + 8];
        int   j0 = sc[k];
        int   j1 = sc[k + 8];
        uint4 u0 = H4[(size_t)j0 * 16 + pos];
        uint4 u1 = H4[(size_t)j1 * 16 + pos];
        ACC8(w0, u0);
        ACC8(w1, u1);
    }
    #undef ACC8

    #pragma unroll
    for (int c = 0; c < 8; c++)
        acc[c] += __shfl_xor_sync(0xffffffffu, acc[c], 16);

    if (half == 0) {
        *reinterpret_cast<float4*>(&accs[w][pos * 8]) =
            make_float4(acc[0], acc[1], acc[2], acc[3]);
        *reinterpret_cast<float4*>(&accs[w][pos * 8 + 4]) =
            make_float4(acc[4], acc[5], acc[6], acc[7]);
    }
    __syncthreads();

    float s = accs[0][tid] + accs[1][tid] + accs[2][tid] + accs[3][tid];
    return s * inv;
}

// ---------------- aggregate0: layer-0 softmax-agg + FUSED layer-1 matvec ---
// out0[i] = relu(agg + b0); h1[i] = out0[i] @ W1 (fp32), stored fp16;
// asrc1/adst1[i] from the same registers.
__global__ __launch_bounds__(128) void aggregate0(const __half* __restrict__ Hh,
                                                  const float* __restrict__ bias,
                                                  float* __restrict__ out,
                                                  const float* __restrict__ W1,
                                                  const float* __restrict__ att_src1,
                                                  const float* __restrict__ att_dst1) {
    const int i    = blockIdx.x;
    const int tid  = threadIdx.x;
    const int lane = tid & 31;
    const int w    = tid >> 5;
    __shared__ float se[MAXNB + 16];
    __shared__ int   sc[MAXNB + 16];
    __shared__ float reds[4];
    __shared__ float accs[4][DD];
    __shared__ float xrow[DD];

    float s = agg_core(Hh, g_asrc0, g_adst0, i, se, sc, reds, accs);
    float o = fmaxf(s + bias[tid], 0.0f);           // bias + relu
    out[(size_t)i * DD + tid] = o;
    xrow[tid] = o;
    __syncthreads();

    // matvec: h1[c] = sum_k xrow[k] * W1[k][c]; warp w covers k in [32w,32w+32)
    const float4* __restrict__ W14 = reinterpret_cast<const float4*>(W1); // 32 float4/row
    float4 m = make_float4(0.f, 0.f, 0.f, 0.f);
    #pragma unroll 8
    for (int kk = 0; kk < 32; kk++) {
        int k = w * 32 + kk;
        float xk = xrow[k];
        float4 wv = W14[k * 32 + lane];
        m.x = fmaf(xk, wv.x, m.x);
        m.y = fmaf(xk, wv.y, m.y);
        m.z = fmaf(xk, wv.z, m.z);
        m.w = fmaf(xk, wv.w, m.w);
    }
    *reinterpret_cast<float4*>(&accs[w][lane * 4]) = m;
    __syncthreads();

    float h1c = accs[0][tid] + accs[1][tid] + accs[2][tid] + accs[3][tid];
    g_h1[(size_t)i * DD + tid] = __float2half(h1c);

    // layer-1 attention coefficients: block reduce
    float ps = h1c * att_src1[tid];
    float pd = h1c * att_dst1[tid];
    #pragma unroll
    for (int oo = 16; oo > 0; oo >>= 1) {
        ps += __shfl_xor_sync(0xffffffffu, ps, oo);
        pd += __shfl_xor_sync(0xffffffffu, pd, oo);
    }
    if (lane == 0) { reds[w] = ps; xrow[w] = pd; }
    __syncthreads();
    if (tid == 0) g_asrc1[i] = reds[0] + reds[1] + reds[2] + reds[3];
    if (tid == 1) g_adst1[i] = xrow[0] + xrow[1] + xrow[2] + xrow[3];
}

// ---------------- aggregate1: plain layer-1 softmax-agg --------------------
__global__ __launch_bounds__(128) void aggregate1(const __half* __restrict__ Hh,
                                                  const float* __restrict__ bias,
                                                  float* __restrict__ out) {
    const int i   = blockIdx.x;
    const int tid = threadIdx.x;
    __shared__ float se[MAXNB + 16];
    __shared__ int   sc[MAXNB + 16];
    __shared__ float reds[4];
    __shared__ float accs[4][DD];

    float s = agg_core(Hh, g_asrc1, g_adst1, i, se, sc, reds, accs);
    out[(size_t)i * DD + tid] = s + bias[tid];
}

// ---------------- launch ---------------------------------------------------
extern "C" void kernel_launch(void* const* d_in, const int* in_sizes, int n_in,
                              void* d_out, int out_size) {
    const float* x        = (const float*)d_in[0];
    const float* adj      = (const float*)d_in[1];
    const float* W0       = (const float*)d_in[2];
    const float* att_src0 = (const float*)d_in[3];
    const float* att_dst0 = (const float*)d_in[4];
    const float* b0       = (const float*)d_in[5];
    const float* W1       = (const float*)d_in[6];
    const float* att_src1 = (const float*)d_in[7];
    const float* att_dst1 = (const float*)d_in[8];
    const float* b1       = (const float*)d_in[9];

    float* out0 = (float*)d_out;
    float* out1 = (float*)d_out + (size_t)NN * DD;

    __half *h0, *h1;
    cudaGetSymbolAddress((void**)&h0, g_h0);
    cudaGetSymbolAddress((void**)&h1, g_h1);

    // build (grid head) + layer-0 GEMM (grid tail) overlap in one launch
    fused_build_gemm<<<BUILD_BLOCKS + GEMM_BLOCKS, 512>>>(adj, x, W0, att_src0, att_dst0, h0);
    // layer-0 aggregate with fused layer-1 feature transform
    aggregate0<<<NN, 128>>>(h0, b0, out0, W1, att_src1, att_dst1);
    // layer-1 aggregate
    aggregate1<<<NN, 128>>>(h1, b1, out1);
}

// round 13
// speedup vs baseline: 1.0678x; 1.0678x over previous
#include <cuda_runtime.h>
#include <cuda_fp16.h>
#include <cstdint>

#define NN 8192
#define DD 128
#define MAXNB 512
#define NEG_SLOPE 0.2f

// ---------------- device scratch (no allocations allowed) ----------------
__device__ __half g_h0[(size_t)NN * DD];   // layer-0 features, fp16
__device__ __half g_h1[(size_t)NN * DD];   // layer-1 features, fp16
__device__ float g_asrc0[NN];
__device__ float g_adst0[NN];
__device__ float g_asrc1[NN];
__device__ float g_adst1[NN];
__device__ int   g_col[(size_t)NN * MAXNB];
__device__ int   g_cnt[NN];

// ---------------- 1) GEMM: h0 = X @ W0 + attention coefficients ------------
// BM=64, BN=128, BK=16, 512 threads, 4x4 outputs/thread, grid=128.
__global__ __launch_bounds__(512) void gemm_xw(const float* __restrict__ X,
                                               const float* __restrict__ W,
                                               const float* __restrict__ att_src,
                                               const float* __restrict__ att_dst,
                                               __half* __restrict__ Hh) {
    __shared__ float As[16][64];
    __shared__ float Bs[16][128];
    const int tid  = threadIdx.x;
    const int lane = tid & 31;
    const int wrp  = tid >> 5;
    const int rowBase = blockIdx.x * 64;

    float acc[4][4];
    #pragma unroll
    for (int i = 0; i < 4; i++)
        #pragma unroll
        for (int j = 0; j < 4; j++) acc[i][j] = 0.0f;

    for (int k0 = 0; k0 < DD; k0 += 16) {
        {
            int r  = tid >> 3;
            int kq = (tid & 7) * 2;
            float2 v = *reinterpret_cast<const float2*>(
                &X[(size_t)(rowBase + r) * DD + k0 + kq]);
            As[kq + 0][r] = v.x;
            As[kq + 1][r] = v.y;
        }
        {
            int kr = tid >> 5;
            int cq = (tid & 31) * 4;
            *reinterpret_cast<float4*>(&Bs[kr][cq]) =
                *reinterpret_cast<const float4*>(&W[(size_t)(k0 + kr) * DD + cq]);
        }
        __syncthreads();
        #pragma unroll
        for (int k = 0; k < 16; k++) {
            float4 a4 = *reinterpret_cast<const float4*>(&As[k][wrp * 4]);
            float4 b4 = *reinterpret_cast<const float4*>(&Bs[k][lane * 4]);
            float a[4] = {a4.x, a4.y, a4.z, a4.w};
            float b[4] = {b4.x, b4.y, b4.z, b4.w};
            #pragma unroll
            for (int i = 0; i < 4; i++)
                #pragma unroll
                for (int j = 0; j < 4; j++)
                    acc[i][j] = fmaf(a[i], b[j], acc[i][j]);
        }
        __syncthreads();
    }

    #pragma unroll
    for (int i = 0; i < 4; i++) {
        __half2 p0 = __float22half2_rn(make_float2(acc[i][0], acc[i][1]));
        __half2 p1 = __float22half2_rn(make_float2(acc[i][2], acc[i][3]));
        uint2 pk;
        pk.x = *reinterpret_cast<unsigned*>(&p0);
        pk.y = *reinterpret_cast<unsigned*>(&p1);
        *reinterpret_cast<uint2*>(&Hh[(size_t)(rowBase + wrp * 4 + i) * DD + lane * 4]) = pk;
    }

    float4 s4 = *reinterpret_cast<const float4*>(&att_src[lane * 4]);
    float4 d4 = *reinterpret_cast<const float4*>(&att_dst[lane * 4]);
    #pragma unroll
    for (int i = 0; i < 4; i++) {
        float ps = acc[i][0] * s4.x + acc[i][1] * s4.y + acc[i][2] * s4.z + acc[i][3] * s4.w;
        float pd = acc[i][0] * d4.x + acc[i][1] * d4.y + acc[i][2] * d4.z + acc[i][3] * d4.w;
        #pragma unroll
        for (int o = 16; o > 0; o >>= 1) {
            ps += __shfl_xor_sync(0xffffffffu, ps, o);
            pd += __shfl_xor_sync(0xffffffffu, pd, o);
        }
        if (lane == 0) {
            g_asrc0[rowBase + wrp * 4 + i] = ps;
            g_adst0[rowBase + wrp * 4 + i] = pd;
        }
    }
}

// ---------------- 2) fused adjacency scan + layer-0 aggregation ------------
// Warp-per-row. One pass over adj row i:
//   - max-free softmax accumulators: sum += exp(e_ij), acc += exp(e_ij)*h0[j]
//   - emit neighbor list for layer 1
// Epilogue: out0 = relu(acc/sum + b0); h1 = out0 @ W1; asrc1/adst1.
__global__ __launch_bounds__(512) void fused_scan_agg0(const float* __restrict__ adj,
                                                       const float* __restrict__ bias,
                                                       float* __restrict__ out0,
                                                       const float* __restrict__ W1,
                                                       const float* __restrict__ att_src1,
                                                       const float* __restrict__ att_dst1) {
    const int w    = threadIdx.x >> 5;
    const int lane = threadIdx.x & 31;
    const int i    = blockIdx.x * 16 + w;

    __shared__ float xs[16][DD];    // per-warp relu'd out0 row for the matvec

    const float4* __restrict__ row4 = reinterpret_cast<const float4*>(adj + (size_t)i * NN);
    const uint2* __restrict__ H0u  = reinterpret_cast<const uint2*>(g_h0);   // 32 per row
    int* __restrict__ col = g_col + (size_t)i * MAXNB;
    const float adst_i = g_adst0[i];

    float acc0 = 0.f, acc1 = 0.f, acc2 = 0.f, acc3 = 0.f;  // channels lane*4..+3
    float sum = 0.0f;                                      // replicated per lane
    int cnt = 0;                                           // replicated per lane

    float4 v = row4[lane];
    for (int chunk = 0; chunk < NN / 128; chunk++) {
        unsigned m0 = __ballot_sync(0xffffffffu, v.x != 0.0f);
        unsigned m1 = __ballot_sync(0xffffffffu, v.y != 0.0f);
        unsigned m2 = __ballot_sync(0xffffffffu, v.z != 0.0f);
        unsigned m3 = __ballot_sync(0xffffffffu, v.w != 0.0f);
        float4 vn;
        if (chunk < NN / 128 - 1) vn = row4[(chunk + 1) * 32 + lane];
        const int base = chunk * 128;

        #define PROC_MASK(mm, off) do {                                        \
            unsigned m = (mm);                                                 \
            while (m) {                                                        \
                int s = __ffs(m) - 1;                                          \
                m &= m - 1;                                                    \
                int j = base + s * 4 + (off);                                  \
                float e = g_asrc0[j] + adst_i;                                 \
                e = e >= 0.0f ? e : NEG_SLOPE * e;                             \
                float wv = __expf(e);                                          \
                sum += wv;                                                     \
                uint2 u = H0u[(size_t)j * 32 + lane];                          \
                __half2 q0 = *reinterpret_cast<const __half2*>(&u.x);          \
                __half2 q1 = *reinterpret_cast<const __half2*>(&u.y);          \
                float2 f0 = __half22float2(q0);                                \
                float2 f1 = __half22float2(q1);                                \
                acc0 = fmaf(wv, f0.x, acc0); acc1 = fmaf(wv, f0.y, acc1);      \
                acc2 = fmaf(wv, f1.x, acc2); acc3 = fmaf(wv, f1.y, acc3);      \
                if (cnt < MAXNB && lane == 0) col[cnt] = j;                    \
                cnt++;                                                         \
            }                                                                  \
        } while (0)

        PROC_MASK(m0, 0);
        PROC_MASK(m1, 1);
        PROC_MASK(m2, 2);
        PROC_MASK(m3, 3);
        #undef PROC_MASK
        v = vn;
    }

    if (lane == 0) g_cnt[i] = cnt < MAXNB ? cnt : MAXNB;

    // epilogue: bias + relu, store out0, stash row for matvec
    const float inv = 1.0f / sum;
    float4 b4 = *reinterpret_cast<const float4*>(&bias[lane * 4]);
    float4 o4;
    o4.x = fmaxf(fmaf(acc0, inv, b4.x), 0.0f);
    o4.y = fmaxf(fmaf(acc1, inv, b4.y), 0.0f);
    o4.z = fmaxf(fmaf(acc2, inv, b4.z), 0.0f);
    o4.w = fmaxf(fmaf(acc3, inv, b4.w), 0.0f);
    reinterpret_cast<float4*>(out0)[(size_t)i * 32 + lane] = o4;
    *reinterpret_cast<float4*>(&xs[w][lane * 4]) = o4;
    __syncwarp();

    // matvec: h1[c] = sum_k xs[k] * W1[k][c]; lane owns c = lane*4..+3
    const float4* __restrict__ W14 = reinterpret_cast<const float4*>(W1);
    float4 m = make_float4(0.f, 0.f, 0.f, 0.f);
    #pragma unroll 4
    for (int k = 0; k < DD; k++) {
        float xk = xs[w][k];
        float4 wv = W14[k * 32 + lane];
        m.x = fmaf(xk, wv.x, m.x);
        m.y = fmaf(xk, wv.y, m.y);
        m.z = fmaf(xk, wv.z, m.z);
        m.w = fmaf(xk, wv.w, m.w);
    }
    {
        __half2 p0 = __float22half2_rn(make_float2(m.x, m.y));
        __half2 p1 = __float22half2_rn(make_float2(m.z, m.w));
        uint2 pk;
        pk.x = *reinterpret_cast<unsigned*>(&p0);
        pk.y = *reinterpret_cast<unsigned*>(&p1);
        *reinterpret_cast<uint2*>(&g_h1[(size_t)i * DD + lane * 4]) = pk;
    }

    // layer-1 attention coefficients: warp reduce
    float4 s4 = *reinterpret_cast<const float4*>(&att_src1[lane * 4]);
    float4 d4 = *reinterpret_cast<const float4*>(&att_dst1[lane * 4]);
    float ps = m.x * s4.x + m.y * s4.y + m.z * s4.z + m.w * s4.w;
    float pd = m.x * d4.x + m.y * d4.y + m.z * d4.z + m.w * d4.w;
    #pragma unroll
    for (int o = 16; o > 0; o >>= 1) {
        ps += __shfl_xor_sync(0xffffffffu, ps, o);
        pd += __shfl_xor_sync(0xffffffffu, pd, o);
    }
    if (lane == 0) {
        g_asrc1[i] = ps;
        g_adst1[i] = pd;
    }
}

// ---------------- 3) layer-1 softmax + aggregation -------------------------
// Block-per-row, 128 threads; max-free softmax, uint4 gathers (R11 design).
__global__ __launch_bounds__(128) void aggregate1(const __half* __restrict__ Hh,
                                                  const float* __restrict__ bias,
                                                  float* __restrict__ out) {
    const int i    = blockIdx.x;
    const int tid  = threadIdx.x;
    const int lane = tid & 31;
    const int w    = tid >> 5;
    const int half = lane >> 4;
    const int pos  = lane & 15;
    __shared__ float se[MAXNB + 16];
    __shared__ int   sc[MAXNB + 16];
    __shared__ float reds[4];
    __shared__ float accs[4][DD];

    const int cnt = g_cnt[i];
    const float adst_i = g_adst1[i];
    const int* __restrict__ col = g_col + (size_t)i * MAXNB;

    float lsum = 0.0f;
    for (int k = tid; k < cnt; k += 128) {
        int j = col[k];
        sc[k] = j;
        float e = g_asrc1[j] + adst_i;
        e = e >= 0.0f ? e : NEG_SLOPE * e;
        float wv = __expf(e);
        se[k] = wv;
        lsum += wv;
    }
    if (tid < 16) { se[cnt + tid] = 0.0f; sc[cnt + tid] = 0; }
    #pragma unroll
    for (int o = 16; o > 0; o >>= 1)
        lsum += __shfl_xor_sync(0xffffffffu, lsum, o);
    if (lane == 0) reds[w] = lsum;
    __syncthreads();
    const float inv = 1.0f / (reds[0] + reds[1] + reds[2] + reds[3]);

    const uint4* __restrict__ H4 = reinterpret_cast<const uint4*>(Hh);
    float acc[8];
    #pragma unroll
    for (int c = 0; c < 8; c++) acc[c] = 0.0f;

    #define ACC8(wv, u) do {                                              \
        __half2 q0 = *reinterpret_cast<const __half2*>(&(u).x);           \
        __half2 q1 = *reinterpret_cast<const __half2*>(&(u).y);           \
        __half2 q2 = *reinterpret_cast<const __half2*>(&(u).z);           \
        __half2 q3 = *reinterpret_cast<const __half2*>(&(u).w);           \
        float2 f0 = __half22float2(q0); float2 f1 = __half22float2(q1);   \
        float2 f2 = __half22float2(q2); float2 f3 = __half22float2(q3);   \
        acc[0] = fmaf((wv), f0.x, acc[0]); acc[1] = fmaf((wv), f0.y, acc[1]); \
        acc[2] = fmaf((wv), f1.x, acc[2]); acc[3] = fmaf((wv), f1.y, acc[3]); \
        acc[4] = fmaf((wv), f2.x, acc[4]); acc[5] = fmaf((wv), f2.y, acc[5]); \
        acc[6] = fmaf((wv), f3.x, acc[6]); acc[7] = fmaf((wv), f3.y, acc[7]); \
    } while (0)

    for (int k = w * 2 + half; k < cnt; k += 16) {
        float w0 = se[k];
        float w1 = se[k + 8];
        int   j0 = sc[k];
        int   j1 = sc[k + 8];
        uint4 u0 = H4[(size_t)j0 * 16 + pos];
        uint4 u1 = H4[(size_t)j1 * 16 + pos];
        ACC8(w0, u0);
        ACC8(w1, u1);
    }
    #undef ACC8

    #pragma unroll
    for (int c = 0; c < 8; c++)
        acc[c] += __shfl_xor_sync(0xffffffffu, acc[c], 16);

    if (half == 0) {
        *reinterpret_cast<float4*>(&accs[w][pos * 8]) =
            make_float4(acc[0], acc[1], acc[2], acc[3]);
        *reinterpret_cast<float4*>(&accs[w][pos * 8 + 4]) =
            make_float4(acc[4], acc[5], acc[6], acc[7]);
    }
    __syncthreads();

    float s = accs[0][tid] + accs[1][tid] + accs[2][tid] + accs[3][tid];
    out[(size_t)i * DD + tid] = fmaf(s, inv, bias[tid]);
}

// ---------------- launch ---------------------------------------------------
extern "C" void kernel_launch(void* const* d_in, const int* in_sizes, int n_in,
                              void* d_out, int out_size) {
    const float* x        = (const float*)d_in[0];
    const float* adj      = (const float*)d_in[1];
    const float* W0       = (const float*)d_in[2];
    const float* att_src0 = (const float*)d_in[3];
    const float* att_dst0 = (const float*)d_in[4];
    const float* b0       = (const float*)d_in[5];
    const float* W1       = (const float*)d_in[6];
    const float* att_src1 = (const float*)d_in[7];
    const float* att_dst1 = (const float*)d_in[8];
    const float* b1       = (const float*)d_in[9];

    float* out0 = (float*)d_out;
    float* out1 = (float*)d_out + (size_t)NN * DD;

    __half *h0, *h1;
    cudaGetSymbolAddress((void**)&h0, g_h0);
    cudaGetSymbolAddress((void**)&h1, g_h1);

    // 1) layer-0 feature transform (needs no adj)
    gemm_xw<<<NN / 64, 512>>>(x, W0, att_src0, att_dst0, h0);
    // 2) single pass over adj: layer-0 aggregation + list build + layer-1 matvec
    fused_scan_agg0<<<NN / 16, 512>>>(adj, b0, out0, W1, att_src1, att_dst1);
    // 3) layer-1 aggregation over the cached lists
    aggregate1<<<NN, 128>>>(h1, b1, out1);
}